// round 2
// baseline (speedup 1.0000x reference)
#include <cuda_runtime.h>

// ---------------------------------------------------------------------------
// IRnet: fused per-control-point conv tower + MLPs, then B-spline dense field.
//
// Structure exploited: the dense conv feature map is only sampled at 8192
// control points x (4x4 bicubic taps). We compute the conv tower only on the
// receptive field of those taps (10x10 input patch per point).
// ---------------------------------------------------------------------------

#define A_CUBIC (-0.75f)

// scratch for disp [B=8][N=1024][2]
__device__ float g_disp[8 * 1024 * 2];

__device__ __forceinline__ float cc1f(float x) {
    return ((A_CUBIC + 2.0f) * x - (A_CUBIC + 3.0f)) * x * x + 1.0f;
}
__device__ __forceinline__ float cc2f(float x) {
    return ((A_CUBIC * x - 5.0f * A_CUBIC) * x + 8.0f * A_CUBIC) * x - 4.0f * A_CUBIC;
}

__global__ __launch_bounds__(256, 2) void fused_point_kernel(
    const float* __restrict__ moving, const float* __restrict__ fixedp,
    const int* __restrict__ cps,
    const float* __restrict__ ce_w1, const float* __restrict__ ce_b1,
    const float* __restrict__ ce_w2, const float* __restrict__ ce_b2,
    const float* __restrict__ ce_w3, const float* __restrict__ ce_b3,
    const float* __restrict__ cv_w1, const float* __restrict__ cv_b1,
    const float* __restrict__ cv_w2, const float* __restrict__ cv_b2,
    const float* __restrict__ cv_w3, const float* __restrict__ cv_b3,
    const float* __restrict__ d_w1, const float* __restrict__ d_b1,
    const float* __restrict__ d_w2, const float* __restrict__ d_b2,
    const float* __restrict__ d_w3, const float* __restrict__ d_b3)
{
    const int W = 512;

    const int bid = blockIdx.x;      // b*1024 + n
    const int b   = bid >> 10;
    const int t   = threadIdx.x;

    __shared__ float s_in[2][10][10];
    __shared__ float s_w1[32 * 2 * 9];
    __shared__ float s_x1[32][8][8];
    __shared__ float s_x2[64][6][6];
    __shared__ float s_feat[64][16];
    __shared__ float s_h1[64];
    __shared__ float s_h2[64];
    __shared__ float s_cat[128];
    __shared__ float s_v1[128];
    __shared__ float s_v2[128];

    // ---- per-point scalars (computed redundantly by every thread) ----
    const int cp0 = cps[bid * 2 + 0];
    const int cp1 = cps[bid * 2 + 1];
    // norm_cp exactly as reference (fp32 op order)
    const float nx = (float)cp0 / 512.0f * 2.0f - 1.0f;
    const float ny = (float)cp1 / 512.0f * 2.0f - 1.0f;
    float ix = (nx + 1.0f) * 0.5f * 511.0f;
    float iy = (ny + 1.0f) * 0.5f * 511.0f;
    ix = fminf(fmaxf(ix, 0.0f), 511.0f);   // reflect_clip is identity in-range
    iy = fminf(fmaxf(iy, 0.0f), 511.0f);
    const int   fx = (int)floorf(ix);
    const int   fy = (int)floorf(iy);
    const float tx = ix - (float)fx;
    const float ty = iy - (float)fy;

    float wx[4] = { cc2f(tx + 1.0f), cc1f(tx), cc1f(1.0f - tx), cc2f(2.0f - tx) };
    float wy[4] = { cc2f(ty + 1.0f), cc1f(ty), cc1f(1.0f - ty), cc2f(2.0f - ty) };

    const int cx0 = min(max(fx - 1, 0), 508);
    const int cy0 = min(max(fy - 1, 0), 508);
    int rx[4], ry[4];
#pragma unroll
    for (int k = 0; k < 4; k++) {
        int vx = fx + k - 1; vx = vx < 0 ? -vx : vx; if (vx > 511) vx = 1022 - vx;
        int vy = fy + k - 1; vy = vy < 0 ? -vy : vy; if (vy > 511) vy = 1022 - vy;
        rx[k] = vx - cx0;   // guaranteed in [0,3]
        ry[k] = vy - cy0;
    }

    // ---- phase 1: load 10x10x2 input patch (zero-padded) + conv1 weights ----
    for (int i = t; i < 200; i += 256) {
        const int ch = i / 100;
        const int r  = (i % 100) / 10;
        const int cc = i % 10;
        const int y = cy0 - 3 + r;
        const int x = cx0 - 3 + cc;
        float v = 0.0f;
        if (y >= 0 && y < 512 && x >= 0 && x < 512) {
            const float* img = (ch == 0) ? moving : fixedp;
            v = img[(b * 512 + y) * W + x];
        }
        s_in[ch][r][cc] = v;
    }
    for (int i = t; i < 576; i += 256) s_w1[i] = cv_w1[i];
    __syncthreads();

    // ---- phase 2: conv1  (2 -> 32, ReLU)  output 8x8 at abs (cy0-2, cx0-2) ----
#pragma unroll
    for (int k = 0; k < 8; k++) {
        const int idx = (k << 8) + t;       // 0..2047
        const int c   = idx >> 6;
        const int pos = idx & 63;
        const int yy  = pos >> 3;
        const int xx  = pos & 7;
        const int ay = cy0 - 2 + yy;
        const int ax = cx0 - 2 + xx;
        float v = 0.0f;
        if (ay >= 0 && ay < 512 && ax >= 0 && ax < 512) {
            float acc = __ldg(&cv_b1[c]);
#pragma unroll
            for (int ci = 0; ci < 2; ci++)
#pragma unroll
                for (int dy = 0; dy < 3; dy++)
#pragma unroll
                    for (int dx = 0; dx < 3; dx++)
                        acc += s_w1[((c * 2 + ci) * 3 + dy) * 3 + dx] *
                               s_in[ci][yy + dy][xx + dx];
            v = fmaxf(acc, 0.0f);
        }
        s_x1[c][yy][xx] = v;
    }
    __syncthreads();

    // ---- phase 3: conv2 (32 -> 64, ReLU)  output 6x6 at abs (cy0-1, cx0-1) ----
    {
        const int c    = t >> 2;
        const int tile = t & 3;
        const int ty0  = (tile >> 1) * 3;
        const int tx0  = (tile & 1) * 3;
        float acc[3][3];
        const float bv = __ldg(&cv_b2[c]);
#pragma unroll
        for (int a = 0; a < 3; a++)
#pragma unroll
            for (int bb = 0; bb < 3; bb++) acc[a][bb] = bv;

        for (int ci = 0; ci < 32; ci++) {
            float in5[5][5];
#pragma unroll
            for (int r = 0; r < 5; r++)
#pragma unroll
                for (int cc = 0; cc < 5; cc++)
                    in5[r][cc] = s_x1[ci][ty0 + r][tx0 + cc];
            const float* wp = cv_w2 + (c * 32 + ci) * 9;
#pragma unroll
            for (int dy = 0; dy < 3; dy++)
#pragma unroll
                for (int dx = 0; dx < 3; dx++) {
                    const float wv = __ldg(wp + dy * 3 + dx);
#pragma unroll
                    for (int a = 0; a < 3; a++)
#pragma unroll
                        for (int bb = 0; bb < 3; bb++)
                            acc[a][bb] += wv * in5[a + dy][bb + dx];
                }
        }
#pragma unroll
        for (int a = 0; a < 3; a++)
#pragma unroll
            for (int bb = 0; bb < 3; bb++) {
                const int oy = ty0 + a, ox = tx0 + bb;
                const int ay = cy0 - 1 + oy, ax = cx0 - 1 + ox;
                float v = 0.0f;
                if (ay >= 0 && ay < 512 && ax >= 0 && ax < 512)
                    v = fmaxf(acc[a][bb], 0.0f);
                s_x2[c][oy][ox] = v;
            }
    }
    __syncthreads();

    // ---- phase 4: conv3 (64 -> 64, linear) output 4x4 at abs (cy0, cx0) ----
    {
        const int c    = t >> 2;
        const int tile = t & 3;
        const int oy0  = (tile >> 1) * 2;
        const int ox0  = (tile & 1) * 2;
        float acc[2][2];
        const float bv = __ldg(&cv_b3[c]);
        acc[0][0] = bv; acc[0][1] = bv; acc[1][0] = bv; acc[1][1] = bv;

        for (int ci = 0; ci < 64; ci++) {
            float in4[4][4];
#pragma unroll
            for (int r = 0; r < 4; r++)
#pragma unroll
                for (int cc = 0; cc < 4; cc++)
                    in4[r][cc] = s_x2[ci][oy0 + r][ox0 + cc];
            const float* wp = cv_w3 + (c * 64 + ci) * 9;
#pragma unroll
            for (int dy = 0; dy < 3; dy++)
#pragma unroll
                for (int dx = 0; dx < 3; dx++) {
                    const float wv = __ldg(wp + dy * 3 + dx);
#pragma unroll
                    for (int a = 0; a < 2; a++)
#pragma unroll
                        for (int bb = 0; bb < 2; bb++)
                            acc[a][bb] += wv * in4[a + dy][bb + dx];
                }
        }
#pragma unroll
        for (int a = 0; a < 2; a++)
#pragma unroll
            for (int bb = 0; bb < 2; bb++)
                s_feat[c][(oy0 + a) * 4 + (ox0 + bb)] = acc[a][bb];
    }
    __syncthreads();

    // ---- phase 5: bicubic reduce + coord-embed layer 1 (in parallel) ----
    if (t < 64) {
        float acc = __ldg(&ce_b1[t]) + __ldg(&ce_w1[t * 2 + 0]) * nx
                                     + __ldg(&ce_w1[t * 2 + 1]) * ny;
        s_h1[t] = fmaxf(acc, 0.0f);
    } else if (t < 128) {
        const int c = t - 64;
        float acc = 0.0f;
#pragma unroll
        for (int i = 0; i < 4; i++)
#pragma unroll
            for (int j = 0; j < 4; j++)
                acc += wy[i] * wx[j] * s_feat[c][ry[i] * 4 + rx[j]];
        s_cat[64 + c] = acc;
    }
    __syncthreads();

    if (t < 64) {
        float acc = __ldg(&ce_b2[t]);
#pragma unroll 8
        for (int i = 0; i < 64; i++) acc += __ldg(&ce_w2[t * 64 + i]) * s_h1[i];
        s_h2[t] = fmaxf(acc, 0.0f);
    }
    __syncthreads();

    if (t < 64) {
        float acc = __ldg(&ce_b3[t]);
#pragma unroll 8
        for (int i = 0; i < 64; i++) acc += __ldg(&ce_w3[t * 64 + i]) * s_h2[i];
        s_cat[t] = acc;
    }
    __syncthreads();

    if (t < 128) {
        float acc = __ldg(&d_b1[t]);
#pragma unroll 8
        for (int i = 0; i < 128; i++) acc += __ldg(&d_w1[t * 128 + i]) * s_cat[i];
        s_v1[t] = fmaxf(acc, 0.0f);
    }
    __syncthreads();

    if (t < 128) {
        float acc = __ldg(&d_b2[t]);
#pragma unroll 8
        for (int i = 0; i < 128; i++) acc += __ldg(&d_w2[t * 128 + i]) * s_v1[i];
        s_v2[t] = fmaxf(acc, 0.0f);
    }
    __syncthreads();

    if (t < 2) {
        float acc = __ldg(&d_b3[t]);
#pragma unroll 8
        for (int i = 0; i < 128; i++) acc += __ldg(&d_w3[t * 128 + i]) * s_v2[i];
        g_disp[bid * 2 + t] = acc;
    }
}

// ---------------------------------------------------------------------------
// B-spline dense field: out[b,h,w,c] = sum_{m,k} wh[h,m]*ww[w,k]*disp[b,ih,iw,c]
// One block per (h, b) row; 4 tap rows of the 32x32 disp grid in smem.
// ---------------------------------------------------------------------------
__global__ __launch_bounds__(256) void bspline_kernel(float2* __restrict__ out)
{
    const int h = blockIdx.x;
    const int b = blockIdx.y;
    const int t = threadIdx.x;

    __shared__ float2 s_rows[4][32];

    const int   i0h = h >> 4;
    const float th  = (float)(h & 15) * (1.0f / 16.0f);

    if (t < 128) {
        const int m  = t >> 5;
        const int pj = t & 31;
        const int row = min(max(i0h + m - 1, 0), 31);
        const float2* gd = (const float2*)g_disp;
        s_rows[m][pj] = gd[b * 1024 + row * 32 + pj];
    }

    const float h2 = th * th, h3 = h2 * th;
    const float wh[4] = {
        (1.0f - th) * (1.0f - th) * (1.0f - th) * (1.0f / 6.0f),
        (3.0f * h3 - 6.0f * h2 + 4.0f) * (1.0f / 6.0f),
        (-3.0f * h3 + 3.0f * h2 + 3.0f * th + 1.0f) * (1.0f / 6.0f),
        h3 * (1.0f / 6.0f)
    };
    __syncthreads();

#pragma unroll
    for (int rep = 0; rep < 2; rep++) {
        const int w   = t + rep * 256;
        const int i0w = w >> 4;
        const float tw = (float)(w & 15) * (1.0f / 16.0f);
        const float s2 = tw * tw, s3 = s2 * tw;
        const float ww[4] = {
            (1.0f - tw) * (1.0f - tw) * (1.0f - tw) * (1.0f / 6.0f),
            (3.0f * s3 - 6.0f * s2 + 4.0f) * (1.0f / 6.0f),
            (-3.0f * s3 + 3.0f * s2 + 3.0f * tw + 1.0f) * (1.0f / 6.0f),
            s3 * (1.0f / 6.0f)
        };
        int iw[4];
#pragma unroll
        for (int k = 0; k < 4; k++) iw[k] = min(max(i0w + k - 1, 0), 31);

        float a0 = 0.0f, a1 = 0.0f;
#pragma unroll
        for (int m = 0; m < 4; m++)
#pragma unroll
            for (int k = 0; k < 4; k++) {
                const float p = wh[m] * ww[k];
                const float2 v = s_rows[m][iw[k]];
                a0 += p * v.x;
                a1 += p * v.y;
            }
        out[(b * 512 + h) * 512 + w] = make_float2(a0, a1);
    }
}

extern "C" void kernel_launch(void* const* d_in, const int* in_sizes, int n_in,
                              void* d_out, int out_size)
{
    const float* moving = (const float*)d_in[0];
    const float* fixedp = (const float*)d_in[1];
    const int*   cps    = (const int*)d_in[2];
    const float* ce_w1 = (const float*)d_in[3];
    const float* ce_b1 = (const float*)d_in[4];
    const float* ce_w2 = (const float*)d_in[5];
    const float* ce_b2 = (const float*)d_in[6];
    const float* ce_w3 = (const float*)d_in[7];
    const float* ce_b3 = (const float*)d_in[8];
    const float* cv_w1 = (const float*)d_in[9];
    const float* cv_b1 = (const float*)d_in[10];
    const float* cv_w2 = (const float*)d_in[11];
    const float* cv_b2 = (const float*)d_in[12];
    const float* cv_w3 = (const float*)d_in[13];
    const float* cv_b3 = (const float*)d_in[14];
    const float* d_w1  = (const float*)d_in[15];
    const float* d_b1  = (const float*)d_in[16];
    const float* d_w2  = (const float*)d_in[17];
    const float* d_b2  = (const float*)d_in[18];
    const float* d_w3  = (const float*)d_in[19];
    const float* d_b3  = (const float*)d_in[20];

    fused_point_kernel<<<8 * 1024, 256>>>(
        moving, fixedp, cps,
        ce_w1, ce_b1, ce_w2, ce_b2, ce_w3, ce_b3,
        cv_w1, cv_b1, cv_w2, cv_b2, cv_w3, cv_b3,
        d_w1, d_b1, d_w2, d_b2, d_w3, d_b3);

    bspline_kernel<<<dim3(512, 8), 256>>>((float2*)d_out);
}

// round 4
// speedup vs baseline: 2.1679x; 2.1679x over previous
#include <cuda_runtime.h>

// ---------------------------------------------------------------------------
// IRnet: fused per-control-point conv tower + MLPs, then B-spline dense field.
// Round 4: 4 points per CTA, all weights staged in smem (transposed, padded).
// Fixed: W1 staging region moved OUT of the X1 span (round-3 bug: conv1 read
// weights from addresses it was concurrently overwriting with x1), and MLP
// activation buffers moved past FEAT's end (kills 2-float feat/H1 race).
// ---------------------------------------------------------------------------

#define A_CUBIC (-0.75f)

// scratch for disp [B=8][N=1024][2]
__device__ float g_disp[8 * 1024 * 2];

__device__ __forceinline__ float cc1f(float x) {
    return ((A_CUBIC + 2.0f) * x - (A_CUBIC + 3.0f)) * x * x + 1.0f;
}
__device__ __forceinline__ float cc2f(float x) {
    return ((A_CUBIC * x - 5.0f * A_CUBIC) * x + 8.0f * A_CUBIC) * x - 4.0f * A_CUBIC;
}

// ---- shared memory layout (float offsets), with liveness:
// A    [0, 37440)      : w2t (conv2) -> w3t (conv3) -> ce_w2/ce_w3/d_w1 -> d_w2
// X1   [37440, 45632)  : conv1 out (live conv1..conv2)
// FEAT [37440, 41796)  : conv3 out (live conv3..bicubic; X1 dead by then)
// H1   [41808, 42072)  : live bicubic..ce2   (inside dead X1, after FEAT end)
// H2   [42072, 42336)  : live ce2..ce3
// CAT  [42336, 42856)  : live bicubic..dispL1
// V1   [42856, 43376)  : live dispL1..dispL2
// V2   [43376, 43896)  : live dispL2..dispL3
// X2   [45632, 54848)  : conv2 out (live conv2..conv3); aliases IN (dead then)
// IN   [45632, 46432)  : input patches (live phase0b..conv1)
// W1   [54848, 55424)  : conv1 weights (live phase0b..conv1) -- own region!
// PT   [55424, 55520)  : per-point scalars
#define OFF_A    0
#define MLP_CE3  4160
#define MLP_DW   8320
#define OFF_X1   37440
#define OFF_FEAT 37440
#define FEAT_GS  1089
#define OFF_H1   41808
#define OFF_H2   42072
#define OFF_CAT  42336
#define OFF_V1   42856
#define OFF_V2   43376
#define OFF_X2   45632
#define OFF_IN   45632
#define OFF_W1   54848
#define OFF_PT   55424
#define SMEM_FLT 55520
#define SMEM_BYTES (SMEM_FLT * 4)

__global__ void __launch_bounds__(256, 1) fused_point_kernel(
    const float* __restrict__ moving, const float* __restrict__ fixedp,
    const int* __restrict__ cps,
    const float* __restrict__ ce_w1, const float* __restrict__ ce_b1,
    const float* __restrict__ ce_w2, const float* __restrict__ ce_b2,
    const float* __restrict__ ce_w3, const float* __restrict__ ce_b3,
    const float* __restrict__ cv_w1, const float* __restrict__ cv_b1,
    const float* __restrict__ cv_w2, const float* __restrict__ cv_b2,
    const float* __restrict__ cv_w3, const float* __restrict__ cv_b3,
    const float* __restrict__ d_w1, const float* __restrict__ d_b1,
    const float* __restrict__ d_w2, const float* __restrict__ d_b2,
    const float* __restrict__ d_w3, const float* __restrict__ d_b3)
{
    extern __shared__ float smem[];

    const int t   = threadIdx.x;
    const int bid = blockIdx.x;          // 2048 CTAs, 4 points each
    const int b   = bid >> 8;            // 256 CTAs per batch

    // ---- phase 0a: per-point scalars ----
    if (t < 4) {
        const int pid = bid * 4 + t;
        const int cp0 = cps[pid * 2 + 0];
        const int cp1 = cps[pid * 2 + 1];
        const float nx = (float)cp0 / 512.0f * 2.0f - 1.0f;
        const float ny = (float)cp1 / 512.0f * 2.0f - 1.0f;
        float ix = (nx + 1.0f) * 0.5f * 511.0f;
        float iy = (ny + 1.0f) * 0.5f * 511.0f;
        ix = fminf(fmaxf(ix, 0.0f), 511.0f);
        iy = fminf(fmaxf(iy, 0.0f), 511.0f);
        const int   fx = (int)floorf(ix);
        const int   fy = (int)floorf(iy);
        const float tx = ix - (float)fx;
        const float ty = iy - (float)fy;
        const int cx0 = min(max(fx - 1, 0), 508);
        const int cy0 = min(max(fy - 1, 0), 508);
        float* p = smem + OFF_PT + t * 24;
        p[0] = nx; p[1] = ny;
        p[2] = cc2f(tx + 1.0f); p[3] = cc1f(tx); p[4] = cc1f(1.0f - tx); p[5] = cc2f(2.0f - tx);
        p[6] = cc2f(ty + 1.0f); p[7] = cc1f(ty); p[8] = cc1f(1.0f - ty); p[9] = cc2f(2.0f - ty);
        p[10] = (float)cx0; p[11] = (float)cy0;
#pragma unroll
        for (int k = 0; k < 4; k++) {
            int vx = fx + k - 1; vx = vx < 0 ? -vx : vx; if (vx > 511) vx = 1022 - vx;
            int vy = fy + k - 1; vy = vy < 0 ? -vy : vy; if (vy > 511) vy = 1022 - vy;
            p[12 + k] = (float)(vx - cx0);
            p[16 + k] = (float)(vy - cy0);
        }
    }
    __syncthreads();

    // ---- phase 0b: stage s_in (800), w1 (576), w2t (18432 -> [ci*9+k][65]+c) ----
    for (int i = t; i < 800; i += 256) {
        const int g  = i / 200;
        const int r2 = i - g * 200;
        const int ch = r2 / 100;
        const int rr = r2 - ch * 100;
        const int cx0 = (int)smem[OFF_PT + g * 24 + 10];
        const int cy0 = (int)smem[OFF_PT + g * 24 + 11];
        const int y = cy0 - 3 + rr / 10;
        const int x = cx0 - 3 + (rr % 10);
        float v = 0.0f;
        if (y >= 0 && y < 512 && x >= 0 && x < 512) {
            const float* img = (ch == 0) ? moving : fixedp;
            v = img[(b * 512 + y) * 512 + x];
        }
        smem[OFF_IN + i] = v;
    }
    for (int i = t; i < 576; i += 256) smem[OFF_W1 + i] = cv_w1[i];
#pragma unroll 1
    for (int j = 0; j < 72; j++) {
        const int gi = t + 256 * j;          // < 18432
        const int c  = gi / 288;
        const int n  = gi - c * 288;         // ci*9 + k
        smem[OFF_A + n * 65 + c] = cv_w2[gi];
    }
    __syncthreads();

    // ---- conv1: 2 -> 32, ReLU.  thread: g = t>>6, pos = t&63 (8x8) ----
    {
        const int g    = t >> 6;
        const int lane = t & 63;
        const int yy = lane >> 3, xx = lane & 7;
        const int cx0 = (int)smem[OFF_PT + g * 24 + 10];
        const int cy0 = (int)smem[OFF_PT + g * 24 + 11];
        const int ay = cy0 - 2 + yy, ax = cx0 - 2 + xx;
        const bool valid = (ay >= 0 && ay < 512 && ax >= 0 && ax < 512);
        float win[2][3][3];
#pragma unroll
        for (int ci = 0; ci < 2; ci++)
#pragma unroll
            for (int dy = 0; dy < 3; dy++)
#pragma unroll
                for (int dx = 0; dx < 3; dx++)
                    win[ci][dy][dx] = smem[OFF_IN + g * 200 + ci * 100 + (yy + dy) * 10 + xx + dx];
#pragma unroll 4
        for (int c = 0; c < 32; c++) {
            float acc = __ldg(&cv_b1[c]);
#pragma unroll
            for (int ci = 0; ci < 2; ci++)
#pragma unroll
                for (int dy = 0; dy < 3; dy++)
#pragma unroll
                    for (int dx = 0; dx < 3; dx++)
                        acc += smem[OFF_W1 + ((c * 2 + ci) * 3 + dy) * 3 + dx] * win[ci][dy][dx];
            smem[OFF_X1 + (g * 32 + c) * 64 + lane] = valid ? fmaxf(acc, 0.0f) : 0.0f;
        }
    }
    __syncthreads();

    // ---- conv2: 32 -> 64, ReLU. thread: g=t>>6, 4 c_out, 3x3 tile ----
    {
        const int g    = t >> 6;
        const int l    = t & 63;
        const int c0   = (l >> 2) * 4;
        const int tile = l & 3;
        const int ty0 = (tile >> 1) * 3, tx0 = (tile & 1) * 3;
        float acc[4][9];
#pragma unroll
        for (int j = 0; j < 4; j++) {
            const float bv = __ldg(&cv_b2[c0 + j]);
#pragma unroll
            for (int p = 0; p < 9; p++) acc[j][p] = bv;
        }
#pragma unroll 1
        for (int ci = 0; ci < 32; ci++) {
            float in5[25];
            const int base = OFF_X1 + (g * 32 + ci) * 64 + ty0 * 8 + tx0;
#pragma unroll
            for (int r = 0; r < 5; r++)
#pragma unroll
                for (int cc = 0; cc < 5; cc++)
                    in5[r * 5 + cc] = smem[base + r * 8 + cc];
            const int wb = OFF_A + ci * 9 * 65 + c0;
#pragma unroll
            for (int k = 0; k < 9; k++) {
                const int dy = k / 3, dx = k % 3;
                const float w0 = smem[wb + k * 65 + 0];
                const float w1v = smem[wb + k * 65 + 1];
                const float w2v = smem[wb + k * 65 + 2];
                const float w3v = smem[wb + k * 65 + 3];
#pragma unroll
                for (int p = 0; p < 9; p++) {
                    const int py = p / 3, px = p % 3;
                    const float v = in5[(py + dy) * 5 + px + dx];
                    acc[0][p] += w0 * v;
                    acc[1][p] += w1v * v;
                    acc[2][p] += w2v * v;
                    acc[3][p] += w3v * v;
                }
            }
        }
        const int cx0 = (int)smem[OFF_PT + g * 24 + 10];
        const int cy0 = (int)smem[OFF_PT + g * 24 + 11];
#pragma unroll
        for (int p = 0; p < 9; p++) {
            const int py = p / 3, px = p % 3;
            const int oy = ty0 + py, ox = tx0 + px;
            const int ay = cy0 - 1 + oy, ax = cx0 - 1 + ox;
            const bool valid = (ay >= 0 && ay < 512 && ax >= 0 && ax < 512);
#pragma unroll
            for (int j = 0; j < 4; j++)
                smem[OFF_X2 + (g * 64 + c0 + j) * 36 + oy * 6 + ox] =
                    valid ? fmaxf(acc[j][p], 0.0f) : 0.0f;
        }
    }
    __syncthreads();

    // ---- stage w3t (36864 -> [ci*9+k][65]+c) ----
#pragma unroll 1
    for (int j = 0; j < 144; j++) {
        const int gi = t + 256 * j;          // < 36864
        const int c  = gi / 576;
        const int n  = gi - c * 576;
        smem[OFF_A + n * 65 + c] = cv_w3[gi];
    }
    __syncthreads();

    // ---- conv3: 64 -> 64, linear. thread: 4 c_out x 2x2 tile ----
    {
        const int g    = t >> 6;
        const int l    = t & 63;
        const int c0   = (l >> 2) * 4;
        const int tile = l & 3;
        const int oy0 = (tile >> 1) * 2, ox0 = (tile & 1) * 2;
        float acc[4][4];
#pragma unroll
        for (int j = 0; j < 4; j++) {
            const float bv = __ldg(&cv_b3[c0 + j]);
#pragma unroll
            for (int p = 0; p < 4; p++) acc[j][p] = bv;
        }
#pragma unroll 1
        for (int ci = 0; ci < 64; ci++) {
            float in4[16];
            const int base = OFF_X2 + (g * 64 + ci) * 36 + oy0 * 6 + ox0;
#pragma unroll
            for (int r = 0; r < 4; r++)
#pragma unroll
                for (int cc = 0; cc < 4; cc++)
                    in4[r * 4 + cc] = smem[base + r * 6 + cc];
            const int wb = OFF_A + ci * 9 * 65 + c0;
#pragma unroll
            for (int k = 0; k < 9; k++) {
                const int dy = k / 3, dx = k % 3;
                const float w0 = smem[wb + k * 65 + 0];
                const float w1v = smem[wb + k * 65 + 1];
                const float w2v = smem[wb + k * 65 + 2];
                const float w3v = smem[wb + k * 65 + 3];
#pragma unroll
                for (int p = 0; p < 4; p++) {
                    const int py = p >> 1, px = p & 1;
                    const float v = in4[(py + dy) * 4 + px + dx];
                    acc[0][p] += w0 * v;
                    acc[1][p] += w1v * v;
                    acc[2][p] += w2v * v;
                    acc[3][p] += w3v * v;
                }
            }
        }
#pragma unroll
        for (int j = 0; j < 4; j++)
#pragma unroll
            for (int p = 0; p < 4; p++) {
                const int py = p >> 1, px = p & 1;
                smem[OFF_FEAT + g * FEAT_GS + (c0 + j) * 17 + (oy0 + py) * 4 + ox0 + px] = acc[j][p];
            }
    }
    __syncthreads();

    // ---- stage MLP weights (ce_w2, ce_w3, d_w1) ----
#pragma unroll 1
    for (int j = 0; j < 16; j++) {
        const int gi = t + 256 * j;          // < 4096
        const int c = gi >> 6, i = gi & 63;
        smem[OFF_A + c * 65 + i] = ce_w2[gi];
    }
#pragma unroll 1
    for (int j = 0; j < 16; j++) {
        const int gi = t + 256 * j;
        const int c = gi >> 6, i = gi & 63;
        smem[OFF_A + MLP_CE3 + c * 65 + i] = ce_w3[gi];
    }
#pragma unroll 1
    for (int j = 0; j < 64; j++) {
        const int gi = t + 256 * j;          // < 16384
        const int c = gi >> 7, i = gi & 127;
        smem[OFF_A + MLP_DW + c * 132 + i] = d_w1[gi];
    }

    // ---- bicubic reduce + ce layer 1 (writes disjoint from FEAT now) ----
    {
        const int c = t >> 2;
        const int g = t & 3;
        const float* p = smem + OFF_PT + g * 24;
        float acc = 0.0f;
#pragma unroll
        for (int i = 0; i < 4; i++) {
            const int ryi = (int)p[16 + i];
            const float wyi = p[6 + i];
#pragma unroll
            for (int j = 0; j < 4; j++) {
                const int rxj = (int)p[12 + j];
                acc += wyi * p[2 + j] * smem[OFF_FEAT + g * FEAT_GS + c * 17 + ryi * 4 + rxj];
            }
        }
        smem[OFF_CAT + g * 130 + 64 + c] = acc;
        const float h = __ldg(&ce_b1[c]) + __ldg(&ce_w1[c * 2 + 0]) * p[0]
                                         + __ldg(&ce_w1[c * 2 + 1]) * p[1];
        smem[OFF_H1 + g * 66 + c] = fmaxf(h, 0.0f);
    }
    __syncthreads();

    // ---- ce layer 2 ----
    {
        const int c = t >> 2, g = t & 3;
        float acc = __ldg(&ce_b2[c]);
#pragma unroll 8
        for (int i = 0; i < 64; i++)
            acc += smem[OFF_A + c * 65 + i] * smem[OFF_H1 + g * 66 + i];
        smem[OFF_H2 + g * 66 + c] = fmaxf(acc, 0.0f);
    }
    __syncthreads();

    // ---- ce layer 3 -> cat[0:64] ----
    {
        const int c = t >> 2, g = t & 3;
        float acc = __ldg(&ce_b3[c]);
#pragma unroll 8
        for (int i = 0; i < 64; i++)
            acc += smem[OFF_A + MLP_CE3 + c * 65 + i] * smem[OFF_H2 + g * 66 + i];
        smem[OFF_CAT + g * 130 + c] = acc;
    }
    __syncthreads();

    // ---- disp layer 1 (128 out, ReLU): 2 outputs per thread ----
    {
        const int c8 = t >> 2, g = t & 3;
#pragma unroll
        for (int rep = 0; rep < 2; rep++) {
            const int c = c8 + 64 * rep;
            float acc = __ldg(&d_b1[c]);
#pragma unroll 8
            for (int i = 0; i < 128; i++)
                acc += smem[OFF_A + MLP_DW + c * 132 + i] * smem[OFF_CAT + g * 130 + i];
            smem[OFF_V1 + g * 130 + c] = fmaxf(acc, 0.0f);
        }
    }
    __syncthreads();

    // ---- stage d_w2 over d_w1 slot ----
#pragma unroll 1
    for (int j = 0; j < 64; j++) {
        const int gi = t + 256 * j;
        const int c = gi >> 7, i = gi & 127;
        smem[OFF_A + MLP_DW + c * 132 + i] = d_w2[gi];
    }
    __syncthreads();

    // ---- disp layer 2 (128 out, ReLU) ----
    {
        const int c8 = t >> 2, g = t & 3;
#pragma unroll
        for (int rep = 0; rep < 2; rep++) {
            const int c = c8 + 64 * rep;
            float acc = __ldg(&d_b2[c]);
#pragma unroll 8
            for (int i = 0; i < 128; i++)
                acc += smem[OFF_A + MLP_DW + c * 132 + i] * smem[OFF_V1 + g * 130 + i];
            smem[OFF_V2 + g * 130 + c] = fmaxf(acc, 0.0f);
        }
    }
    __syncthreads();

    // ---- disp layer 3 (2 out) -> g_disp ----
    if (t < 8) {
        const int g = t >> 1, c = t & 1;
        float acc = __ldg(&d_b3[c]);
#pragma unroll 8
        for (int i = 0; i < 128; i++)
            acc += __ldg(&d_w3[c * 128 + i]) * smem[OFF_V2 + g * 130 + i];
        g_disp[(bid * 4 + g) * 2 + c] = acc;
    }
}

// ---------------------------------------------------------------------------
// B-spline dense field (unchanged; measured 10.6us).
// ---------------------------------------------------------------------------
__global__ __launch_bounds__(256) void bspline_kernel(float2* __restrict__ out)
{
    const int h = blockIdx.x;
    const int b = blockIdx.y;
    const int t = threadIdx.x;

    __shared__ float2 s_rows[4][32];

    const int   i0h = h >> 4;
    const float th  = (float)(h & 15) * (1.0f / 16.0f);

    if (t < 128) {
        const int m  = t >> 5;
        const int pj = t & 31;
        const int row = min(max(i0h + m - 1, 0), 31);
        const float2* gd = (const float2*)g_disp;
        s_rows[m][pj] = gd[b * 1024 + row * 32 + pj];
    }

    const float h2 = th * th, h3 = h2 * th;
    const float wh[4] = {
        (1.0f - th) * (1.0f - th) * (1.0f - th) * (1.0f / 6.0f),
        (3.0f * h3 - 6.0f * h2 + 4.0f) * (1.0f / 6.0f),
        (-3.0f * h3 + 3.0f * h2 + 3.0f * th + 1.0f) * (1.0f / 6.0f),
        h3 * (1.0f / 6.0f)
    };
    __syncthreads();

#pragma unroll
    for (int rep = 0; rep < 2; rep++) {
        const int w   = t + rep * 256;
        const int i0w = w >> 4;
        const float tw = (float)(w & 15) * (1.0f / 16.0f);
        const float s2 = tw * tw, s3 = s2 * tw;
        const float ww[4] = {
            (1.0f - tw) * (1.0f - tw) * (1.0f - tw) * (1.0f / 6.0f),
            (3.0f * s3 - 6.0f * s2 + 4.0f) * (1.0f / 6.0f),
            (-3.0f * s3 + 3.0f * s2 + 3.0f * tw + 1.0f) * (1.0f / 6.0f),
            s3 * (1.0f / 6.0f)
        };
        int iw[4];
#pragma unroll
        for (int k = 0; k < 4; k++) iw[k] = min(max(i0w + k - 1, 0), 31);

        float a0 = 0.0f, a1 = 0.0f;
#pragma unroll
        for (int m = 0; m < 4; m++)
#pragma unroll
            for (int k = 0; k < 4; k++) {
                const float p = wh[m] * ww[k];
                const float2 v = s_rows[m][iw[k]];
                a0 += p * v.x;
                a1 += p * v.y;
            }
        out[(b * 512 + h) * 512 + w] = make_float2(a0, a1);
    }
}

extern "C" void kernel_launch(void* const* d_in, const int* in_sizes, int n_in,
                              void* d_out, int out_size)
{
    const float* moving = (const float*)d_in[0];
    const float* fixedp = (const float*)d_in[1];
    const int*   cps    = (const int*)d_in[2];
    const float* ce_w1 = (const float*)d_in[3];
    const float* ce_b1 = (const float*)d_in[4];
    const float* ce_w2 = (const float*)d_in[5];
    const float* ce_b2 = (const float*)d_in[6];
    const float* ce_w3 = (const float*)d_in[7];
    const float* ce_b3 = (const float*)d_in[8];
    const float* cv_w1 = (const float*)d_in[9];
    const float* cv_b1 = (const float*)d_in[10];
    const float* cv_w2 = (const float*)d_in[11];
    const float* cv_b2 = (const float*)d_in[12];
    const float* cv_w3 = (const float*)d_in[13];
    const float* cv_b3 = (const float*)d_in[14];
    const float* d_w1  = (const float*)d_in[15];
    const float* d_b1  = (const float*)d_in[16];
    const float* d_w2  = (const float*)d_in[17];
    const float* d_b2  = (const float*)d_in[18];
    const float* d_w3  = (const float*)d_in[19];
    const float* d_b3  = (const float*)d_in[20];

    cudaFuncSetAttribute(fused_point_kernel,
                         cudaFuncAttributeMaxDynamicSharedMemorySize, SMEM_BYTES);

    fused_point_kernel<<<2048, 256, SMEM_BYTES>>>(
        moving, fixedp, cps,
        ce_w1, ce_b1, ce_w2, ce_b2, ce_w3, ce_b3,
        cv_w1, cv_b1, cv_w2, cv_b2, cv_w3, cv_b3,
        d_w1, d_b1, d_w2, d_b2, d_w3, d_b3);

    bspline_kernel<<<dim3(512, 8), 256>>>((float2*)d_out);
}